// round 5
// baseline (speedup 1.0000x reference)
#include <cuda_runtime.h>
#include <cstdint>

#define B_     8
#define NQ_    12544
#define NKV_   12544
#define C_     128
#define H_     112
#define WI_    224
#define NINIT_ 50176
#define NS_    784
#define HS_    28
#define INV4_  (1.0f/(4.0f+1e-06f))

typedef unsigned long long u64;

// ---------------- packed f32x2 helpers (sm_100a) ----------------------------
__device__ __forceinline__ u64 pk2(float lo, float hi){
    u64 r; asm("mov.b64 %0, {%1, %2};" : "=l"(r) : "f"(lo), "f"(hi)); return r;
}
__device__ __forceinline__ void fma2(u64& d, u64 a, u64 b){
    asm("fma.rn.f32x2 %0, %1, %2, %0;" : "+l"(d) : "l"(a), "l"(b));
}
__device__ __forceinline__ void mul2(u64& d, u64 s){
    asm("mul.rn.f32x2 %0, %0, %1;" : "+l"(d) : "l"(s));
}
__device__ __forceinline__ float2 up2(u64 v){
    float lo, hi; asm("mov.b64 {%0, %1}, %2;" : "=f"(lo), "=f"(hi) : "l"(v));
    return make_float2(lo, hi);
}

// ---------------- scratch (device globals; allocations are forbidden) ------
static __device__ float g_q  [B_*NQ_*C_];    // q_x @ q_w * SCALE  (col = h*64+d)
static __device__ float g_map[B_*H_*H_*C_];  // kv map, channel-last [b][y][x][c]
static __device__ float g_wt [2048*128];     // sr_w transposed: [(p*128+c)][o]
static __device__ float g_kvr[B_*NS_*C_];    // conv output, token-major
static __device__ float g_k  [B_*2*NS_*64];  // [b][h][s][d]
static __device__ float g_v  [B_*2*NS_*64];
static __device__ float g_conf[B_*NS_];
static __device__ float g_ao [B_*NQ_*C_];    // attention out (col = h*64+d)

// ---------------- sr_w transpose: [o][c][ky][kx] -> [(p*128+c)][o] ----------
__global__ void k_wt(const float* __restrict__ srw){
    int idx = blockIdx.x * blockDim.x + threadIdx.x;
    if (idx >= 2048*128) return;
    int p = idx & 15, c = (idx >> 4) & 127, o = idx >> 11;
    g_wt[(p*128 + c)*128 + o] = srw[idx];
}

// ---------------- token2map: each map cell = avg of 4 gathered tokens ------
__global__ __launch_bounds__(128) void k_t2m(const float* __restrict__ kvx,
                                             const int* __restrict__ idx){
    int warp = threadIdx.x >> 5, lane = threadIdx.x & 31;
    int cell = blockIdx.x * 4 + warp;          // = b*12544 + y*112 + x
    int b  = cell / (H_*H_);
    int yx = cell % (H_*H_);
    int y = yx / H_, x = yx % H_;
    const int* ib = idx + (size_t)b*NINIT_ + (2*y)*WI_ + 2*x;
    int i0 = ib[0], i1 = ib[1], i2 = ib[WI_], i3 = ib[WI_+1];
    const float* base = kvx + (size_t)b*NKV_*C_;
    int c4 = lane * 4;
    float4 a = *(const float4*)(base + (size_t)i0*C_ + c4);
    float4 bb= *(const float4*)(base + (size_t)i1*C_ + c4);
    float4 cc= *(const float4*)(base + (size_t)i2*C_ + c4);
    float4 dd= *(const float4*)(base + (size_t)i3*C_ + c4);
    float4 o;
    o.x = (a.x+bb.x+cc.x+dd.x)*INV4_;
    o.y = (a.y+bb.y+cc.y+dd.y)*INV4_;
    o.z = (a.z+bb.z+cc.z+dd.z)*INV4_;
    o.w = (a.w+bb.w+cc.w+dd.w)*INV4_;
    *(float4*)(g_map + (size_t)cell*C_ + c4) = o;
}

// ---------------- conf: pooled token_score over the 8x8 init block ----------
__global__ __launch_bounds__(128) void k_conf(const float* __restrict__ score,
                                              const int* __restrict__ idx){
    int warp = threadIdx.x >> 5, lane = threadIdx.x & 31;
    int sidx = blockIdx.x * 4 + warp;           // < B_*NS_
    int b = sidx / NS_, s = sidx % NS_;
    int ii = s / HS_, jj = s % HS_;
    const int* ib = idx + (size_t)b*NINIT_;
    float sum = 0.f;
#pragma unroll
    for (int rep = 0; rep < 2; rep++){
        int p = lane + rep*32;                  // 0..63 within 8x8 block
        int rr = p >> 3, cc = p & 7;
        int tok = ib[(8*ii + rr)*WI_ + 8*jj + cc];
        sum += score[(size_t)b*NKV_ + tok];
    }
#pragma unroll
    for (int off = 16; off >= 1; off >>= 1)
        sum += __shfl_xor_sync(0xffffffffu, sum, off);
    if (lane == 0) g_conf[sidx] = sum * (INV4_ * (1.0f/16.0f));
}

// ---------------- generic Mx128 @ 128x128 GEMM, 64-row tiles, f32x2 ---------
__device__ __forceinline__ void gemm128_body(const float* __restrict__ A,
                                             const float* __restrict__ W,
                                             const float* __restrict__ bias,
                                             float alpha, float* __restrict__ Cout){
    __shared__ __align__(16) float sA[32*64];   // [k][m]
    __shared__ __align__(16) float sW[32*128];  // [k][n]
    int t  = threadIdx.x;
    int tx = t & 15, ty = t >> 4;
    size_t m0 = (size_t)blockIdx.x * 64;
    int lr = t >> 2, lc = (t & 3) * 8;
    u64 acc2[4][4];
#pragma unroll
    for (int i = 0; i < 4; i++)
#pragma unroll
        for (int j = 0; j < 4; j++) acc2[i][j] = 0ull;

    for (int q = 0; q < 4; q++){
        __syncthreads();
        const float* ap = A + (m0 + lr)*128 + q*32 + lc;
        float4 a0 = *(const float4*)ap;
        float4 a1 = *(const float4*)(ap + 4);
        sA[(lc+0)*64+lr]=a0.x; sA[(lc+1)*64+lr]=a0.y; sA[(lc+2)*64+lr]=a0.z; sA[(lc+3)*64+lr]=a0.w;
        sA[(lc+4)*64+lr]=a1.x; sA[(lc+5)*64+lr]=a1.y; sA[(lc+6)*64+lr]=a1.z; sA[(lc+7)*64+lr]=a1.w;
#pragma unroll
        for (int u = 0; u < 4; u++){
            int pos = u*256 + t; int kk = pos >> 5; int c4 = (pos & 31)*4;
            *(float4*)(sW + kk*128 + c4) = *(const float4*)(W + (size_t)(q*32+kk)*128 + c4);
        }
        __syncthreads();
#pragma unroll 4
        for (int kk = 0; kk < 32; kk++){
            float4 av = *(const float4*)(sA + kk*64 + ty*4);
            ulonglong2 wA = *(const ulonglong2*)(sW + kk*128 + tx*8);
            ulonglong2 wB = *(const ulonglong2*)(sW + kk*128 + tx*8 + 4);
            u64 b0 = pk2(av.x,av.x), b1 = pk2(av.y,av.y);
            u64 b2 = pk2(av.z,av.z), b3 = pk2(av.w,av.w);
            fma2(acc2[0][0],b0,wA.x); fma2(acc2[0][1],b0,wA.y);
            fma2(acc2[0][2],b0,wB.x); fma2(acc2[0][3],b0,wB.y);
            fma2(acc2[1][0],b1,wA.x); fma2(acc2[1][1],b1,wA.y);
            fma2(acc2[1][2],b1,wB.x); fma2(acc2[1][3],b1,wB.y);
            fma2(acc2[2][0],b2,wA.x); fma2(acc2[2][1],b2,wA.y);
            fma2(acc2[2][2],b2,wB.x); fma2(acc2[2][3],b2,wB.y);
            fma2(acc2[3][0],b3,wA.x); fma2(acc2[3][1],b3,wA.y);
            fma2(acc2[3][2],b3,wB.x); fma2(acc2[3][3],b3,wB.y);
        }
    }
#pragma unroll
    for (int i = 0; i < 4; i++){
        size_t m = m0 + ty*4 + i;
        float* cp = Cout + m*128 + tx*8;
        float2 f0 = up2(acc2[i][0]), f1 = up2(acc2[i][1]);
        float2 f2 = up2(acc2[i][2]), f3 = up2(acc2[i][3]);
        float4 o0, o1;
        o0.x = f0.x*alpha + (bias ? bias[tx*8+0] : 0.f);
        o0.y = f0.y*alpha + (bias ? bias[tx*8+1] : 0.f);
        o0.z = f1.x*alpha + (bias ? bias[tx*8+2] : 0.f);
        o0.w = f1.y*alpha + (bias ? bias[tx*8+3] : 0.f);
        o1.x = f2.x*alpha + (bias ? bias[tx*8+4] : 0.f);
        o1.y = f2.y*alpha + (bias ? bias[tx*8+5] : 0.f);
        o1.z = f3.x*alpha + (bias ? bias[tx*8+6] : 0.f);
        o1.w = f3.y*alpha + (bias ? bias[tx*8+7] : 0.f);
        *(float4*)cp       = o0;
        *(float4*)(cp + 4) = o1;
    }
}

__global__ __launch_bounds__(256) void k_qproj(const float* __restrict__ A,
                                               const float* __restrict__ W){
    gemm128_body(A, W, nullptr, 0.125f, g_q);   // SCALE = 64^-0.5 folded in
}
__global__ __launch_bounds__(256) void k_oproj(const float* __restrict__ W,
                                               const float* __restrict__ bias,
                                               float* __restrict__ out){
    gemm128_body(g_ao, W, bias, 1.0f, out);
}

// ---------------- conv as GEMM: [6272 x 2048] @ [2048 x 128], f32x2 ---------
__global__ __launch_bounds__(256) void k_conv(const float* __restrict__ bias){
    __shared__ __align__(16) float sA[32*64];
    __shared__ __align__(16) float sW[32*128];
    int t  = threadIdx.x;
    int tx = t & 15, ty = t >> 4;
    int m0 = blockIdx.x * 64;
    int lr = t >> 2, lc = (t & 3) * 8;
    int m  = m0 + lr;
    int b  = m / NS_; int s = m % NS_;
    int ii = s / HS_, jj = s % HS_;
    size_t base0 = (((size_t)b*H_ + 4*ii)*H_ + 4*jj)*C_;
    u64 acc2[4][4];
#pragma unroll
    for (int i = 0; i < 4; i++)
#pragma unroll
        for (int j = 0; j < 4; j++) acc2[i][j] = 0ull;

    for (int q = 0; q < 64; q++){
        int p  = q >> 2;            // patch cell 0..15 (ky*4+kx)
        int c0 = (q & 3) * 32;      // channel offset
        int ky = p >> 2, kx = p & 3;
        __syncthreads();
        const float* ap = g_map + base0 + (size_t)(ky*H_ + kx)*C_ + c0 + lc;
        float4 a0 = *(const float4*)ap;
        float4 a1 = *(const float4*)(ap + 4);
        sA[(lc+0)*64+lr]=a0.x; sA[(lc+1)*64+lr]=a0.y; sA[(lc+2)*64+lr]=a0.z; sA[(lc+3)*64+lr]=a0.w;
        sA[(lc+4)*64+lr]=a1.x; sA[(lc+5)*64+lr]=a1.y; sA[(lc+6)*64+lr]=a1.z; sA[(lc+7)*64+lr]=a1.w;
        const float* wp = g_wt + (size_t)q*32*128;
#pragma unroll
        for (int u = 0; u < 4; u++){
            int pos = u*256 + t; int kk = pos >> 5; int c4 = (pos & 31)*4;
            *(float4*)(sW + kk*128 + c4) = *(const float4*)(wp + kk*128 + c4);
        }
        __syncthreads();
#pragma unroll 4
        for (int kk = 0; kk < 32; kk++){
            float4 av = *(const float4*)(sA + kk*64 + ty*4);
            ulonglong2 wA = *(const ulonglong2*)(sW + kk*128 + tx*8);
            ulonglong2 wB = *(const ulonglong2*)(sW + kk*128 + tx*8 + 4);
            u64 b0 = pk2(av.x,av.x), b1 = pk2(av.y,av.y);
            u64 b2 = pk2(av.z,av.z), b3 = pk2(av.w,av.w);
            fma2(acc2[0][0],b0,wA.x); fma2(acc2[0][1],b0,wA.y);
            fma2(acc2[0][2],b0,wB.x); fma2(acc2[0][3],b0,wB.y);
            fma2(acc2[1][0],b1,wA.x); fma2(acc2[1][1],b1,wA.y);
            fma2(acc2[1][2],b1,wB.x); fma2(acc2[1][3],b1,wB.y);
            fma2(acc2[2][0],b2,wA.x); fma2(acc2[2][1],b2,wA.y);
            fma2(acc2[2][2],b2,wB.x); fma2(acc2[2][3],b2,wB.y);
            fma2(acc2[3][0],b3,wA.x); fma2(acc2[3][1],b3,wA.y);
            fma2(acc2[3][2],b3,wB.x); fma2(acc2[3][3],b3,wB.y);
        }
    }
#pragma unroll
    for (int i = 0; i < 4; i++){
        size_t mm = (size_t)m0 + ty*4 + i;
        float* cp = g_kvr + mm*128 + tx*8;
        float2 f0 = up2(acc2[i][0]), f1 = up2(acc2[i][1]);
        float2 f2 = up2(acc2[i][2]), f3 = up2(acc2[i][3]);
        float4 o0, o1;
        o0.x = f0.x + bias[tx*8+0]; o0.y = f0.y + bias[tx*8+1];
        o0.z = f1.x + bias[tx*8+2]; o0.w = f1.y + bias[tx*8+3];
        o1.x = f2.x + bias[tx*8+4]; o1.y = f2.y + bias[tx*8+5];
        o1.z = f3.x + bias[tx*8+6]; o1.w = f3.y + bias[tx*8+7];
        *(float4*)cp       = o0;
        *(float4*)(cp + 4) = o1;
    }
}

// ---------------- LayerNorm + kv projection (16 rows / block) ---------------
__global__ __launch_bounds__(256) void k_lnkv(const float* __restrict__ kvw,
                                              const float* __restrict__ gamma,
                                              const float* __restrict__ beta){
    __shared__ __align__(16) float sY[16*128];
    int t = threadIdx.x; int warp = t >> 5, lane = t & 31;
    int row0 = blockIdx.x * 16;
#pragma unroll
    for (int rr = 0; rr < 2; rr++){
        int r = warp*2 + rr;
        size_t grow = (size_t)row0 + r;
        const float* xp = g_kvr + grow*128 + lane*4;
        float4 xv = *(const float4*)xp;
        float s1 = xv.x + xv.y + xv.z + xv.w;
        float s2 = xv.x*xv.x + xv.y*xv.y + xv.z*xv.z + xv.w*xv.w;
#pragma unroll
        for (int off = 16; off >= 1; off >>= 1){
            s1 += __shfl_xor_sync(0xffffffffu, s1, off);
            s2 += __shfl_xor_sync(0xffffffffu, s2, off);
        }
        float mean = s1 * (1.0f/128.0f);
        float var  = s2 * (1.0f/128.0f) - mean*mean;
        float rstd = rsqrtf(var + 1e-5f);
        int c = lane * 4;
        float4 gv = *(const float4*)(gamma + c);
        float4 bv = *(const float4*)(beta  + c);
        float4 y;
        y.x = (xv.x - mean)*rstd*gv.x + bv.x;
        y.y = (xv.y - mean)*rstd*gv.y + bv.y;
        y.z = (xv.z - mean)*rstd*gv.z + bv.z;
        y.w = (xv.w - mean)*rstd*gv.w + bv.w;
        *(float4*)(sY + r*128 + c) = y;
    }
    __syncthreads();
    // Y[16x128] @ kvw[128x256]; thread t owns column c = t
    int c = t;
    float acc[16];
#pragma unroll
    for (int r = 0; r < 16; r++) acc[r] = 0.f;
    for (int kk = 0; kk < 128; kk++){
        float w = kvw[(size_t)kk*256 + c];
#pragma unroll
        for (int r = 0; r < 16; r++) acc[r] += sY[r*128 + kk] * w;
    }
    int kvsel = c >> 7, rem = c & 127;
    int h = rem >> 6, d = rem & 63;
    float* dst = kvsel ? g_v : g_k;
#pragma unroll
    for (int r = 0; r < 16; r++){
        int grow = row0 + r;                    // = b*784 + s
        int b = grow / NS_, s = grow % NS_;
        dst[((size_t)(b*2 + h)*NS_ + s)*64 + d] = acc[r];
    }
}

// ---------------- flash attention: 64 queries x 1 head per block ------------
#define SMEM_ATTN_BYTES ((64*64 + 64*128 + 128*64 + 128)*4)
__global__ __launch_bounds__(256, 2) void k_attn(){
    extern __shared__ float sm[];
    float* sQ  = sm;             // [d][q] 64x64
    float* sKT = sQ + 64*64;     // [d][k] 64x128  (aliased by P [q][k] later)
    float* sV  = sKT + 64*128;   // [k][d] 128x64
    float* sC  = sV + 128*64;    // [128]
    int t = threadIdx.x;
    int qt = blockIdx.x, h = blockIdx.y, b = blockIdx.z;
    int tx = t & 15, ty = t >> 4;
    {   // load Q tile transposed
        int lr = t >> 2, lc = (t & 3) * 16;
        const float* gp = g_q + ((size_t)(b*NQ_ + qt*64 + lr))*128 + h*64 + lc;
#pragma unroll
        for (int j = 0; j < 4; j++){
            float4 v = *(const float4*)(gp + j*4);
            sQ[(lc + j*4 + 0)*64 + lr] = v.x;
            sQ[(lc + j*4 + 1)*64 + lr] = v.y;
            sQ[(lc + j*4 + 2)*64 + lr] = v.z;
            sQ[(lc + j*4 + 3)*64 + lr] = v.w;
        }
    }
    float m[4], l[4];
    u64 o2[4][2];                // packed O accumulators (d pairs)
#pragma unroll
    for (int i = 0; i < 4; i++){
        m[i] = -1e30f; l[i] = 0.f;
        o2[i][0] = 0ull; o2[i][1] = 0ull;
    }
    const float* Kbase = g_k + (size_t)(b*2+h)*NS_*64;
    const float* Vbase = g_v + (size_t)(b*2+h)*NS_*64;

    for (int ch = 0; ch < 7; ch++){
        int k0 = ch*128;
        int nvalid = NS_ - k0; if (nvalid > 128) nvalid = 128;
        __syncthreads();                       // prior PV reads done
        {   // load K^T (scatter) and V (copy); zero-pad invalid keys
            int kk = t >> 1, dc = (t & 1)*32;
            if (kk < nvalid){
                const float* kp = Kbase + (size_t)(k0+kk)*64 + dc;
#pragma unroll
                for (int j = 0; j < 8; j++){
                    float4 v = *(const float4*)(kp + j*4);
                    sKT[(dc+j*4+0)*128 + kk] = v.x;
                    sKT[(dc+j*4+1)*128 + kk] = v.y;
                    sKT[(dc+j*4+2)*128 + kk] = v.z;
                    sKT[(dc+j*4+3)*128 + kk] = v.w;
                }
                const float* vp = Vbase + (size_t)(k0+kk)*64 + dc;
                float4* sv = (float4*)(sV + kk*64 + dc);
#pragma unroll
                for (int j = 0; j < 8; j++) sv[j] = *(const float4*)(vp + j*4);
            } else {
#pragma unroll
                for (int j = 0; j < 8; j++){
                    sKT[(dc+j*4+0)*128+kk]=0.f; sKT[(dc+j*4+1)*128+kk]=0.f;
                    sKT[(dc+j*4+2)*128+kk]=0.f; sKT[(dc+j*4+3)*128+kk]=0.f;
                }
                float4 z = make_float4(0.f,0.f,0.f,0.f);
                float4* sv = (float4*)(sV + kk*64 + dc);
#pragma unroll
                for (int j = 0; j < 8; j++) sv[j] = z;
            }
            if (t < 128) sC[t] = (k0 + t < NS_) ? g_conf[b*NS_ + k0 + t] : 0.f;
        }
        __syncthreads();
        // S = Q @ K^T  (thread tile 4q x 8k), packed along k
        u64 s2[4][4];
#pragma unroll
        for (int i = 0; i < 4; i++)
#pragma unroll
            for (int j = 0; j < 4; j++) s2[i][j] = 0ull;
#pragma unroll 4
        for (int d = 0; d < 64; d++){
            float4 qv = *(const float4*)(sQ  + d*64  + ty*4);
            ulonglong2 kA = *(const ulonglong2*)(sKT + d*128 + tx*8);
            ulonglong2 kB = *(const ulonglong2*)(sKT + d*128 + tx*8 + 4);
            u64 q0 = pk2(qv.x,qv.x), q1 = pk2(qv.y,qv.y);
            u64 q2 = pk2(qv.z,qv.z), q3 = pk2(qv.w,qv.w);
            fma2(s2[0][0],q0,kA.x); fma2(s2[0][1],q0,kA.y);
            fma2(s2[0][2],q0,kB.x); fma2(s2[0][3],q0,kB.y);
            fma2(s2[1][0],q1,kA.x); fma2(s2[1][1],q1,kA.y);
            fma2(s2[1][2],q1,kB.x); fma2(s2[1][3],q1,kB.y);
            fma2(s2[2][0],q2,kA.x); fma2(s2[2][1],q2,kA.y);
            fma2(s2[2][2],q2,kB.x); fma2(s2[2][3],q2,kB.y);
            fma2(s2[3][0],q3,kA.x); fma2(s2[3][1],q3,kA.y);
            fma2(s2[3][2],q3,kB.x); fma2(s2[3][3],q3,kB.y);
        }
        float acc[4][8];
#pragma unroll
        for (int i = 0; i < 4; i++)
#pragma unroll
            for (int jp = 0; jp < 4; jp++){
                float2 f = up2(s2[i][jp]);
                acc[i][2*jp]   = f.x;
                acc[i][2*jp+1] = f.y;
            }
        // online softmax (conf bias + tail mask)
#pragma unroll
        for (int i = 0; i < 4; i++){
            float rm = -1e30f;
#pragma unroll
            for (int j = 0; j < 8; j++){
                int kg = k0 + tx*8 + j;
                float s = (kg < NS_) ? (acc[i][j] + sC[tx*8+j]) : -1e30f;
                acc[i][j] = s;
                rm = fmaxf(rm, s);
            }
#pragma unroll
            for (int off = 8; off >= 1; off >>= 1)
                rm = fmaxf(rm, __shfl_xor_sync(0xffffffffu, rm, off, 16));
            float mn = fmaxf(m[i], rm);
            float sc = __expf(m[i] - mn);
            float rs = 0.f;
#pragma unroll
            for (int j = 0; j < 8; j++){
                float p = __expf(acc[i][j] - mn);
                acc[i][j] = p;
                rs += p;
            }
#pragma unroll
            for (int off = 8; off >= 1; off >>= 1)
                rs += __shfl_xor_sync(0xffffffffu, rs, off, 16);
            l[i] = l[i]*sc + rs;
            m[i] = mn;
            u64 sc2 = pk2(sc, sc);
            mul2(o2[i][0], sc2);
            mul2(o2[i][1], sc2);
        }
        __syncthreads();                       // everyone done reading sKT
        {   // write P into sKT's space
#pragma unroll
            for (int i = 0; i < 4; i++){
                float4 p0 = make_float4(acc[i][0],acc[i][1],acc[i][2],acc[i][3]);
                float4 p1 = make_float4(acc[i][4],acc[i][5],acc[i][6],acc[i][7]);
                float4* pp = (float4*)(sKT + (ty*4+i)*128 + tx*8);
                pp[0] = p0; pp[1] = p1;
            }
        }
        __syncthreads();
        // O += P @ V  (thread tile 4q x 4d), packed along d
        const float* sP = sKT;
#pragma unroll 2
        for (int k = 0; k < 128; k += 4){
            float4 pr[4];
#pragma unroll
            for (int i = 0; i < 4; i++) pr[i] = *(const float4*)(sP + (ty*4+i)*128 + k);
            ulonglong2 v0 = *(const ulonglong2*)(sV + (k+0)*64 + tx*4);
            ulonglong2 v1 = *(const ulonglong2*)(sV + (k+1)*64 + tx*4);
            ulonglong2 v2 = *(const ulonglong2*)(sV + (k+2)*64 + tx*4);
            ulonglong2 v3 = *(const ulonglong2*)(sV + (k+3)*64 + tx*4);
#pragma unroll
            for (int i = 0; i < 4; i++){
                u64 p0 = pk2(pr[i].x, pr[i].x);
                u64 p1 = pk2(pr[i].y, pr[i].y);
                u64 p2 = pk2(pr[i].z, pr[i].z);
                u64 p3 = pk2(pr[i].w, pr[i].w);
                fma2(o2[i][0], p0, v0.x); fma2(o2[i][1], p0, v0.y);
                fma2(o2[i][0], p1, v1.x); fma2(o2[i][1], p1, v1.y);
                fma2(o2[i][0], p2, v2.x); fma2(o2[i][1], p2, v2.y);
                fma2(o2[i][0], p3, v3.x); fma2(o2[i][1], p3, v3.y);
            }
        }
    }
#pragma unroll
    for (int i = 0; i < 4; i++){
        float inv = 1.0f / l[i];
        float2 a = up2(o2[i][0]);
        float2 c = up2(o2[i][1]);
        float4 ov = make_float4(a.x*inv, a.y*inv, c.x*inv, c.y*inv);
        *(float4*)(g_ao + ((size_t)(b*NQ_ + qt*64 + ty*4 + i))*128 + h*64 + tx*4) = ov;
    }
}

// ---------------- host launcher --------------------------------------------
extern "C" void kernel_launch(void* const* d_in, const int* in_sizes, int n_in,
                              void* d_out, int out_size) {
    const float *q_x=0,*kv_x=0,*score=0,*q_w=0,*kv_w=0,*proj_w=0,*proj_b=0,
                *sr_w=0,*sr_b=0,*norm_g=0,*norm_b=0;
    const int* idx = 0;
    int c12m = 0, c16k = 0, c128 = 0;
    for (int i = 0; i < n_in; i++){
        int s = in_sizes[i];
        const void* p = d_in[i];
        if (s == 12845056){ if (c12m++ == 0) q_x = (const float*)p; else kv_x = (const float*)p; }
        else if (s == 100352) score = (const float*)p;
        else if (s == 401408) idx = (const int*)p;
        else if (s == 16384){ if (c16k++ == 0) q_w = (const float*)p; else proj_w = (const float*)p; }
        else if (s == 32768) kv_w = (const float*)p;
        else if (s == 262144) sr_w = (const float*)p;
        else if (s == 128){
            if      (c128 == 0) proj_b = (const float*)p;
            else if (c128 == 1) sr_b   = (const float*)p;
            else if (c128 == 2) norm_g = (const float*)p;
            else                norm_b = (const float*)p;
            c128++;
        }
        // sizes 1 (H, W, H_init, W_init) are fixed constants; ignored
    }

    cudaFuncSetAttribute(k_attn, cudaFuncAttributeMaxDynamicSharedMemorySize,
                         SMEM_ATTN_BYTES);

    k_wt  <<<2048, 128>>>(sr_w);
    k_t2m <<<25088, 128>>>(kv_x, idx);
    k_conf<<<1568, 128>>>(score, idx);
    k_qproj<<<1568, 256>>>(q_x, q_w);
    k_conv<<<98, 256>>>(sr_b);
    k_lnkv<<<392, 256>>>(kv_w, norm_g, norm_b);
    k_attn<<<dim3(196, 2, 8), 256, SMEM_ATTN_BYTES>>>();
    k_oproj<<<1568, 256>>>(proj_w, proj_b, (float*)d_out);
}

// round 9
// speedup vs baseline: 2.5943x; 2.5943x over previous
#include <cuda_runtime.h>
#include <cstdint>

// R9 == R8 resubmission (infra flake suspected; artifact unchanged for attribution)

#define B_     8
#define NQ_    12544
#define NKV_   12544
#define C_     128
#define H_     112
#define WI_    224
#define NINIT_ 50176
#define NS_    784
#define HS_    28
#define INV4_  (1.0f/(4.0f+1e-06f))

typedef unsigned long long u64;

// ---------------- packed f32x2 helpers (sm_100) ------------------------------
__device__ __forceinline__ u64 pk2(float lo, float hi){
    u64 r; asm("mov.b64 %0, {%1, %2};" : "=l"(r) : "f"(lo), "f"(hi)); return r;
}
__device__ __forceinline__ void fma2(u64& d, u64 a, u64 b){
    asm("fma.rn.f32x2 %0, %1, %2, %0;" : "+l"(d) : "l"(a), "l"(b));
}
__device__ __forceinline__ float2 up2(u64 v){
    float lo, hi; asm("mov.b64 {%0, %1}, %2;" : "=f"(lo), "=f"(hi) : "l"(v));
    return make_float2(lo, hi);
}

// ---------------- tf32 mma.sync helpers (sm_80+, legal on sm_100) ------------
__device__ __forceinline__ uint32_t tf32r(float f){
    uint32_t u; asm("cvt.rna.tf32.f32 %0, %1;" : "=r"(u) : "f"(f)); return u;
}
__device__ __forceinline__ void mma8(float* d, const uint32_t* a,
                                     uint32_t b0, uint32_t b1){
    asm volatile("mma.sync.aligned.m16n8k8.row.col.f32.tf32.tf32.f32 "
        "{%0,%1,%2,%3}, {%4,%5,%6,%7}, {%8,%9}, {%0,%1,%2,%3};"
        : "+f"(d[0]), "+f"(d[1]), "+f"(d[2]), "+f"(d[3])
        : "r"(a[0]), "r"(a[1]), "r"(a[2]), "r"(a[3]), "r"(b0), "r"(b1));
}

// ---------------- scratch (device globals; allocations are forbidden) ------
static __device__ float g_q  [B_*NQ_*C_];    // q_x @ q_w * SCALE (col = h*64+d)
static __device__ float g_map[B_*H_*H_*C_];
static __device__ float g_wt [2048*128];
static __device__ float g_kvr[B_*NS_*C_];
static __device__ float g_k  [B_*2*NS_*64];  // [b][h][s][d]
static __device__ float g_v  [B_*2*NS_*64];  // [b][h][s][d]
static __device__ float g_conf[B_*NS_];
static __device__ float g_ao [B_*NQ_*C_];

// ---------------- sr_w transpose -------------------------------------------
__global__ void k_wt(const float* __restrict__ srw){
    int idx = blockIdx.x * blockDim.x + threadIdx.x;
    if (idx >= 2048*128) return;
    int p = idx & 15, c = (idx >> 4) & 127, o = idx >> 11;
    g_wt[(p*128 + c)*128 + o] = srw[idx];
}

// ---------------- token2map -------------------------------------------------
__global__ __launch_bounds__(128) void k_t2m(const float* __restrict__ kvx,
                                             const int* __restrict__ idx){
    int warp = threadIdx.x >> 5, lane = threadIdx.x & 31;
    int cell = blockIdx.x * 4 + warp;
    int b  = cell / (H_*H_);
    int yx = cell % (H_*H_);
    int y = yx / H_, x = yx % H_;
    const int* ib = idx + (size_t)b*NINIT_ + (2*y)*WI_ + 2*x;
    int i0 = ib[0], i1 = ib[1], i2 = ib[WI_], i3 = ib[WI_+1];
    const float* base = kvx + (size_t)b*NKV_*C_;
    int c4 = lane * 4;
    float4 a = *(const float4*)(base + (size_t)i0*C_ + c4);
    float4 bb= *(const float4*)(base + (size_t)i1*C_ + c4);
    float4 cc= *(const float4*)(base + (size_t)i2*C_ + c4);
    float4 dd= *(const float4*)(base + (size_t)i3*C_ + c4);
    float4 o;
    o.x = (a.x+bb.x+cc.x+dd.x)*INV4_;
    o.y = (a.y+bb.y+cc.y+dd.y)*INV4_;
    o.z = (a.z+bb.z+cc.z+dd.z)*INV4_;
    o.w = (a.w+bb.w+cc.w+dd.w)*INV4_;
    *(float4*)(g_map + (size_t)cell*C_ + c4) = o;
}

// ---------------- conf ------------------------------------------------------
__global__ __launch_bounds__(128) void k_conf(const float* __restrict__ score,
                                              const int* __restrict__ idx){
    int warp = threadIdx.x >> 5, lane = threadIdx.x & 31;
    int sidx = blockIdx.x * 4 + warp;
    int b = sidx / NS_, s = sidx % NS_;
    int ii = s / HS_, jj = s % HS_;
    const int* ib = idx + (size_t)b*NINIT_;
    float sum = 0.f;
#pragma unroll
    for (int rep = 0; rep < 2; rep++){
        int p = lane + rep*32;
        int rr = p >> 3, cc = p & 7;
        int tok = ib[(8*ii + rr)*WI_ + 8*jj + cc];
        sum += score[(size_t)b*NKV_ + tok];
    }
#pragma unroll
    for (int off = 16; off >= 1; off >>= 1)
        sum += __shfl_xor_sync(0xffffffffu, sum, off);
    if (lane == 0) g_conf[sidx] = sum * (INV4_ * (1.0f/16.0f));
}

// ---------------- generic Mx128 @ 128x128 GEMM, f32x2 -----------------------
__device__ __forceinline__ void gemm128_body(const float* __restrict__ A,
                                             const float* __restrict__ W,
                                             const float* __restrict__ bias,
                                             float alpha, float* __restrict__ Cout){
    __shared__ __align__(16) float sA[32*64];
    __shared__ __align__(16) float sW[32*128];
    int t  = threadIdx.x;
    int tx = t & 15, ty = t >> 4;
    size_t m0 = (size_t)blockIdx.x * 64;
    int lr = t >> 2, lc = (t & 3) * 8;
    u64 acc2[4][4];
#pragma unroll
    for (int i = 0; i < 4; i++)
#pragma unroll
        for (int j = 0; j < 4; j++) acc2[i][j] = 0ull;

    for (int q = 0; q < 4; q++){
        __syncthreads();
        const float* ap = A + (m0 + lr)*128 + q*32 + lc;
        float4 a0 = *(const float4*)ap;
        float4 a1 = *(const float4*)(ap + 4);
        sA[(lc+0)*64+lr]=a0.x; sA[(lc+1)*64+lr]=a0.y; sA[(lc+2)*64+lr]=a0.z; sA[(lc+3)*64+lr]=a0.w;
        sA[(lc+4)*64+lr]=a1.x; sA[(lc+5)*64+lr]=a1.y; sA[(lc+6)*64+lr]=a1.z; sA[(lc+7)*64+lr]=a1.w;
#pragma unroll
        for (int u = 0; u < 4; u++){
            int pos = u*256 + t; int kk = pos >> 5; int c4 = (pos & 31)*4;
            *(float4*)(sW + kk*128 + c4) = *(const float4*)(W + (size_t)(q*32+kk)*128 + c4);
        }
        __syncthreads();
#pragma unroll 4
        for (int kk = 0; kk < 32; kk++){
            float4 av = *(const float4*)(sA + kk*64 + ty*4);
            ulonglong2 wA = *(const ulonglong2*)(sW + kk*128 + tx*8);
            ulonglong2 wB = *(const ulonglong2*)(sW + kk*128 + tx*8 + 4);
            u64 b0 = pk2(av.x,av.x), b1 = pk2(av.y,av.y);
            u64 b2 = pk2(av.z,av.z), b3 = pk2(av.w,av.w);
            fma2(acc2[0][0],b0,wA.x); fma2(acc2[0][1],b0,wA.y);
            fma2(acc2[0][2],b0,wB.x); fma2(acc2[0][3],b0,wB.y);
            fma2(acc2[1][0],b1,wA.x); fma2(acc2[1][1],b1,wA.y);
            fma2(acc2[1][2],b1,wB.x); fma2(acc2[1][3],b1,wB.y);
            fma2(acc2[2][0],b2,wA.x); fma2(acc2[2][1],b2,wA.y);
            fma2(acc2[2][2],b2,wB.x); fma2(acc2[2][3],b2,wB.y);
            fma2(acc2[3][0],b3,wA.x); fma2(acc2[3][1],b3,wA.y);
            fma2(acc2[3][2],b3,wB.x); fma2(acc2[3][3],b3,wB.y);
        }
    }
#pragma unroll
    for (int i = 0; i < 4; i++){
        size_t m = m0 + ty*4 + i;
        float* cp = Cout + m*128 + tx*8;
        float2 f0 = up2(acc2[i][0]), f1 = up2(acc2[i][1]);
        float2 f2 = up2(acc2[i][2]), f3 = up2(acc2[i][3]);
        float4 o0, o1;
        o0.x = f0.x*alpha + (bias ? bias[tx*8+0] : 0.f);
        o0.y = f0.y*alpha + (bias ? bias[tx*8+1] : 0.f);
        o0.z = f1.x*alpha + (bias ? bias[tx*8+2] : 0.f);
        o0.w = f1.y*alpha + (bias ? bias[tx*8+3] : 0.f);
        o1.x = f2.x*alpha + (bias ? bias[tx*8+4] : 0.f);
        o1.y = f2.y*alpha + (bias ? bias[tx*8+5] : 0.f);
        o1.z = f3.x*alpha + (bias ? bias[tx*8+6] : 0.f);
        o1.w = f3.y*alpha + (bias ? bias[tx*8+7] : 0.f);
        *(float4*)cp       = o0;
        *(float4*)(cp + 4) = o1;
    }
}

__global__ __launch_bounds__(256) void k_qproj(const float* __restrict__ A,
                                               const float* __restrict__ W){
    gemm128_body(A, W, nullptr, 0.125f, g_q);
}
__global__ __launch_bounds__(256) void k_oproj(const float* __restrict__ W,
                                               const float* __restrict__ bias,
                                               float* __restrict__ out){
    gemm128_body(g_ao, W, bias, 1.0f, out);
}

// ---------------- conv as GEMM ----------------------------------------------
__global__ __launch_bounds__(256) void k_conv(const float* __restrict__ bias){
    __shared__ __align__(16) float sA[32*64];
    __shared__ __align__(16) float sW[32*128];
    int t  = threadIdx.x;
    int tx = t & 15, ty = t >> 4;
    int m0 = blockIdx.x * 64;
    int lr = t >> 2, lc = (t & 3) * 8;
    int m  = m0 + lr;
    int b  = m / NS_; int s = m % NS_;
    int ii = s / HS_, jj = s % HS_;
    size_t base0 = (((size_t)b*H_ + 4*ii)*H_ + 4*jj)*C_;
    u64 acc2[4][4];
#pragma unroll
    for (int i = 0; i < 4; i++)
#pragma unroll
        for (int j = 0; j < 4; j++) acc2[i][j] = 0ull;

    for (int q = 0; q < 64; q++){
        int p  = q >> 2;
        int c0 = (q & 3) * 32;
        int ky = p >> 2, kx = p & 3;
        __syncthreads();
        const float* ap = g_map + base0 + (size_t)(ky*H_ + kx)*C_ + c0 + lc;
        float4 a0 = *(const float4*)ap;
        float4 a1 = *(const float4*)(ap + 4);
        sA[(lc+0)*64+lr]=a0.x; sA[(lc+1)*64+lr]=a0.y; sA[(lc+2)*64+lr]=a0.z; sA[(lc+3)*64+lr]=a0.w;
        sA[(lc+4)*64+lr]=a1.x; sA[(lc+5)*64+lr]=a1.y; sA[(lc+6)*64+lr]=a1.z; sA[(lc+7)*64+lr]=a1.w;
        const float* wp = g_wt + (size_t)q*32*128;
#pragma unroll
        for (int u = 0; u < 4; u++){
            int pos = u*256 + t; int kk = pos >> 5; int c4 = (pos & 31)*4;
            *(float4*)(sW + kk*128 + c4) = *(const float4*)(wp + kk*128 + c4);
        }
        __syncthreads();
#pragma unroll 4
        for (int kk = 0; kk < 32; kk++){
            float4 av = *(const float4*)(sA + kk*64 + ty*4);
            ulonglong2 wA = *(const ulonglong2*)(sW + kk*128 + tx*8);
            ulonglong2 wB = *(const ulonglong2*)(sW + kk*128 + tx*8 + 4);
            u64 b0 = pk2(av.x,av.x), b1 = pk2(av.y,av.y);
            u64 b2 = pk2(av.z,av.z), b3 = pk2(av.w,av.w);
            fma2(acc2[0][0],b0,wA.x); fma2(acc2[0][1],b0,wA.y);
            fma2(acc2[0][2],b0,wB.x); fma2(acc2[0][3],b0,wB.y);
            fma2(acc2[1][0],b1,wA.x); fma2(acc2[1][1],b1,wA.y);
            fma2(acc2[1][2],b1,wB.x); fma2(acc2[1][3],b1,wB.y);
            fma2(acc2[2][0],b2,wA.x); fma2(acc2[2][1],b2,wA.y);
            fma2(acc2[2][2],b2,wB.x); fma2(acc2[2][3],b2,wB.y);
            fma2(acc2[3][0],b3,wA.x); fma2(acc2[3][1],b3,wA.y);
            fma2(acc2[3][2],b3,wB.x); fma2(acc2[3][3],b3,wB.y);
        }
    }
#pragma unroll
    for (int i = 0; i < 4; i++){
        size_t mm = (size_t)m0 + ty*4 + i;
        float* cp = g_kvr + mm*128 + tx*8;
        float2 f0 = up2(acc2[i][0]), f1 = up2(acc2[i][1]);
        float2 f2 = up2(acc2[i][2]), f3 = up2(acc2[i][3]);
        float4 o0, o1;
        o0.x = f0.x + bias[tx*8+0]; o0.y = f0.y + bias[tx*8+1];
        o0.z = f1.x + bias[tx*8+2]; o0.w = f1.y + bias[tx*8+3];
        o1.x = f2.x + bias[tx*8+4]; o1.y = f2.y + bias[tx*8+5];
        o1.z = f3.x + bias[tx*8+6]; o1.w = f3.y + bias[tx*8+7];
        *(float4*)cp       = o0;
        *(float4*)(cp + 4) = o1;
    }
}

// ---------------- LayerNorm + kv projection ---------------------------------
__global__ __launch_bounds__(256) void k_lnkv(const float* __restrict__ kvw,
                                              const float* __restrict__ gamma,
                                              const float* __restrict__ beta){
    __shared__ __align__(16) float sY[16*128];
    int t = threadIdx.x; int warp = t >> 5, lane = t & 31;
    int row0 = blockIdx.x * 16;
#pragma unroll
    for (int rr = 0; rr < 2; rr++){
        int r = warp*2 + rr;
        size_t grow = (size_t)row0 + r;
        const float* xp = g_kvr + grow*128 + lane*4;
        float4 xv = *(const float4*)xp;
        float s1 = xv.x + xv.y + xv.z + xv.w;
        float s2 = xv.x*xv.x + xv.y*xv.y + xv.z*xv.z + xv.w*xv.w;
#pragma unroll
        for (int off = 16; off >= 1; off >>= 1){
            s1 += __shfl_xor_sync(0xffffffffu, s1, off);
            s2 += __shfl_xor_sync(0xffffffffu, s2, off);
        }
        float mean = s1 * (1.0f/128.0f);
        float var  = s2 * (1.0f/128.0f) - mean*mean;
        float rstd = rsqrtf(var + 1e-5f);
        int c = lane * 4;
        float4 gv = *(const float4*)(gamma + c);
        float4 bv = *(const float4*)(beta  + c);
        float4 y;
        y.x = (xv.x - mean)*rstd*gv.x + bv.x;
        y.y = (xv.y - mean)*rstd*gv.y + bv.y;
        y.z = (xv.z - mean)*rstd*gv.z + bv.z;
        y.w = (xv.w - mean)*rstd*gv.w + bv.w;
        *(float4*)(sY + r*128 + c) = y;
    }
    __syncthreads();
    int c = t;
    float acc[16];
#pragma unroll
    for (int r = 0; r < 16; r++) acc[r] = 0.f;
    for (int kk = 0; kk < 128; kk++){
        float w = kvw[(size_t)kk*256 + c];
#pragma unroll
        for (int r = 0; r < 16; r++) acc[r] += sY[r*128 + kk] * w;
    }
    int kvsel = c >> 7, rem = c & 127;
    int h = rem >> 6, d = rem & 63;
    float* dst = kvsel ? g_v : g_k;
#pragma unroll
    for (int r = 0; r < 16; r++){
        int grow = row0 + r;
        int b = grow / NS_, s = grow % NS_;
        dst[((size_t)(b*2 + h)*NS_ + s)*64 + d] = acc[r];
    }
}

// ---------------- flash attention via tf32 mma.sync -------------------------
// block = 128 queries x 1 head, 256 threads (8 warps x m16); 64-key chunks
// smem: sC[64]f @0, sK[64x68]u @256, sV[64x72]u @17664, sP[128x68]u @36096
#define SMEM_ATTN_MMA 70912
__global__ __launch_bounds__(256, 2) void k_attn(){
    extern __shared__ __align__(16) char smem[];
    float*    sC = (float*)smem;
    uint32_t* sK = (uint32_t*)(smem + 256);
    uint32_t* sV = (uint32_t*)(smem + 17664);
    uint32_t* sP = (uint32_t*)(smem + 36096);
    int t = threadIdx.x, w = t >> 5, lane = t & 31;
    int g = lane >> 2, c = lane & 3;
    int qt = blockIdx.x, h = blockIdx.y, b = blockIdx.z;
    int r0 = w*16 + g;                       // first of this thread's 2 rows

    // Q fragments in registers for the whole kernel
    uint32_t qf[8][4];
    const float* Qb = g_q + ((size_t)b*NQ_ + (size_t)qt*128)*128 + h*64;
#pragma unroll
    for (int kk = 0; kk < 8; kk++){
        qf[kk][0] = tf32r(Qb[(size_t)r0    *128 + kk*8 + c]);
        qf[kk][1] = tf32r(Qb[(size_t)(r0+8)*128 + kk*8 + c]);
        qf[kk][2] = tf32r(Qb[(size_t)r0    *128 + kk*8 + c + 4]);
        qf[kk][3] = tf32r(Qb[(size_t)(r0+8)*128 + kk*8 + c + 4]);
    }
    float of[8][4];
#pragma unroll
    for (int i = 0; i < 8; i++){ of[i][0]=0.f; of[i][1]=0.f; of[i][2]=0.f; of[i][3]=0.f; }
    float m0 = -1e30f, m1 = -1e30f, l0 = 0.f, l1 = 0.f;

    const float* Kb = g_k + (size_t)(b*2+h)*NS_*64;
    const float* Vb = g_v + (size_t)(b*2+h)*NS_*64;

    for (int ch = 0; ch < 13; ch++){
        int k0 = ch*64;
        int nvalid = NS_ - k0; if (nvalid > 64) nvalid = 64;
        __syncthreads();
        // stage K,V as tf32 bits (zero-pad invalid rows)
#pragma unroll
        for (int i = 0; i < 4; i++){
            int idx4 = i*256 + t;            // 1024 float4 total
            int row = idx4 >> 4, d4 = (idx4 & 15)*4;
            float4 kv = make_float4(0.f,0.f,0.f,0.f);
            float4 vv = make_float4(0.f,0.f,0.f,0.f);
            if (row < nvalid){
                kv = *(const float4*)(Kb + (size_t)(k0+row)*64 + d4);
                vv = *(const float4*)(Vb + (size_t)(k0+row)*64 + d4);
            }
            uint4 ku = make_uint4(tf32r(kv.x), tf32r(kv.y), tf32r(kv.z), tf32r(kv.w));
            uint4 vu = make_uint4(tf32r(vv.x), tf32r(vv.y), tf32r(vv.z), tf32r(vv.w));
            *(uint4*)(sK + row*68 + d4) = ku;
            *(uint4*)(sV + row*72 + d4) = vu;
        }
        if (t < 64) sC[t] = (k0 + t < NS_) ? g_conf[b*NS_ + k0 + t] : 0.f;
        __syncthreads();

        // S = Q @ K^T : 8 n-tiles x 8 k-steps of m16n8k8
        float sacc[8][4];
#pragma unroll
        for (int j = 0; j < 8; j++){ sacc[j][0]=0.f; sacc[j][1]=0.f; sacc[j][2]=0.f; sacc[j][3]=0.f; }
#pragma unroll
        for (int j = 0; j < 8; j++){
#pragma unroll
            for (int kk = 0; kk < 8; kk++){
                uint32_t b0 = sK[(8*j+g)*68 + kk*8 + c];
                uint32_t b1 = sK[(8*j+g)*68 + kk*8 + c + 4];
                mma8(sacc[j], qf[kk], b0, b1);
            }
        }

        // online softmax (rows r0, r0+8; quad lanes share a row)
        float rm0 = -1e30f, rm1 = -1e30f;
#pragma unroll
        for (int j = 0; j < 8; j++){
            int col0 = 8*j + 2*c, col1 = col0 + 1;
            float bias0 = sC[col0], bias1 = sC[col1];
            float s0 = (col0 < nvalid) ? sacc[j][0] + bias0 : -1e30f;
            float s1 = (col1 < nvalid) ? sacc[j][1] + bias1 : -1e30f;
            float s2 = (col0 < nvalid) ? sacc[j][2] + bias0 : -1e30f;
            float s3 = (col1 < nvalid) ? sacc[j][3] + bias1 : -1e30f;
            sacc[j][0]=s0; sacc[j][1]=s1; sacc[j][2]=s2; sacc[j][3]=s3;
            rm0 = fmaxf(rm0, fmaxf(s0, s1));
            rm1 = fmaxf(rm1, fmaxf(s2, s3));
        }
        rm0 = fmaxf(rm0, __shfl_xor_sync(0xffffffffu, rm0, 1));
        rm0 = fmaxf(rm0, __shfl_xor_sync(0xffffffffu, rm0, 2));
        rm1 = fmaxf(rm1, __shfl_xor_sync(0xffffffffu, rm1, 1));
        rm1 = fmaxf(rm1, __shfl_xor_sync(0xffffffffu, rm1, 2));
        float mn0 = fmaxf(m0, rm0), mn1 = fmaxf(m1, rm1);
        float sc0 = __expf(m0 - mn0), sc1 = __expf(m1 - mn1);
        m0 = mn0; m1 = mn1;
        float rs0 = 0.f, rs1 = 0.f;
#pragma unroll
        for (int j = 0; j < 8; j++){
            int col0 = 8*j + 2*c;
            float p0 = __expf(sacc[j][0] - mn0);
            float p1 = __expf(sacc[j][1] - mn0);
            float p2 = __expf(sacc[j][2] - mn1);
            float p3 = __expf(sacc[j][3] - mn1);
            rs0 += p0 + p1; rs1 += p2 + p3;
            sP[(size_t)r0*68 + col0]       = tf32r(p0);
            sP[(size_t)r0*68 + col0 + 1]   = tf32r(p1);
            sP[(size_t)(r0+8)*68 + col0]   = tf32r(p2);
            sP[(size_t)(r0+8)*68 + col0+1] = tf32r(p3);
        }
        rs0 += __shfl_xor_sync(0xffffffffu, rs0, 1);
        rs0 += __shfl_xor_sync(0xffffffffu, rs0, 2);
        rs1 += __shfl_xor_sync(0xffffffffu, rs1, 1);
        rs1 += __shfl_xor_sync(0xffffffffu, rs1, 2);
        l0 = l0*sc0 + rs0;
        l1 = l1*sc1 + rs1;
#pragma unroll
        for (int dt = 0; dt < 8; dt++){
            of[dt][0] *= sc0; of[dt][1] *= sc0;
            of[dt][2] *= sc1; of[dt][3] *= sc1;
        }
        __syncwarp();   // sP region is per-warp-private: warp-level sync suffices

        // O += P @ V : 8 k-steps x 8 d-tiles
#pragma unroll
        for (int kk = 0; kk < 8; kk++){
            uint32_t a[4];
            a[0] = sP[(size_t)r0    *68 + kk*8 + c];
            a[1] = sP[(size_t)(r0+8)*68 + kk*8 + c];
            a[2] = sP[(size_t)r0    *68 + kk*8 + c + 4];
            a[3] = sP[(size_t)(r0+8)*68 + kk*8 + c + 4];
#pragma unroll
            for (int dt = 0; dt < 8; dt++){
                uint32_t b0 = sV[(kk*8+c)*72   + dt*8 + g];
                uint32_t b1 = sV[(kk*8+c+4)*72 + dt*8 + g];
                mma8(of[dt], a, b0, b1);
            }
        }
    }

    float inv0 = 1.0f / l0, inv1 = 1.0f / l1;
    float* op = g_ao + ((size_t)b*NQ_ + (size_t)qt*128)*128 + h*64;
#pragma unroll
    for (int dt = 0; dt < 8; dt++){
        *(float2*)(op + (size_t)r0*128 + dt*8 + 2*c) =
            make_float2(of[dt][0]*inv0, of[dt][1]*inv0);
        *(float2*)(op + (size_t)(r0+8)*128 + dt*8 + 2*c) =
            make_float2(of[dt][2]*inv1, of[dt][3]*inv1);
    }
}

// ---------------- host launcher --------------------------------------------
extern "C" void kernel_launch(void* const* d_in, const int* in_sizes, int n_in,
                              void* d_out, int out_size) {
    const float *q_x=0,*kv_x=0,*score=0,*q_w=0,*kv_w=0,*proj_w=0,*proj_b=0,
                *sr_w=0,*sr_b=0,*norm_g=0,*norm_b=0;
    const int* idx = 0;
    int c12m = 0, c16k = 0, c128 = 0;
    for (int i = 0; i < n_in; i++){
        int s = in_sizes[i];
        const void* p = d_in[i];
        if (s == 12845056){ if (c12m++ == 0) q_x = (const float*)p; else kv_x = (const float*)p; }
        else if (s == 100352) score = (const float*)p;
        else if (s == 401408) idx = (const int*)p;
        else if (s == 16384){ if (c16k++ == 0) q_w = (const float*)p; else proj_w = (const float*)p; }
        else if (s == 32768) kv_w = (const float*)p;
        else if (s == 262144) sr_w = (const float*)p;
        else if (s == 128){
            if      (c128 == 0) proj_b = (const float*)p;
            else if (c128 == 1) sr_b   = (const float*)p;
            else if (c128 == 2) norm_g = (const float*)p;
            else                norm_b = (const float*)p;
            c128++;
        }
    }

    cudaFuncSetAttribute(k_attn, cudaFuncAttributeMaxDynamicSharedMemorySize,
                         SMEM_ATTN_MMA);

    k_wt  <<<2048, 128>>>(sr_w);
    k_t2m <<<25088, 128>>>(kv_x, idx);
    k_conf<<<1568, 128>>>(score, idx);
    k_qproj<<<1568, 256>>>(q_x, q_w);
    k_conv<<<98, 256>>>(sr_b);
    k_lnkv<<<392, 256>>>(kv_w, norm_g, norm_b);
    k_attn<<<dim3(98, 2, 8), 256, SMEM_ATTN_MMA>>>();
    k_oproj<<<1568, 256>>>(proj_w, proj_b, (float*)d_out);
}